// round 12
// baseline (speedup 1.0000x reference)
#include <cuda_runtime.h>
#include <cstdint>

// BaseEncoder: out[b, f, c] = (bitcast<u32>(x[b,f]) >> (31 - c)) & 1  (float).
// c==0 is bit 31 (sign == (x<0) channel); c>=1 are bits 30..0 of |x|.
//
// Floor analysis (R8/R10): 264 MB crosses SM<->L2 at ~6.35 TB/s = the
// measured path-independent LTS chip cap; ~41.5 us kernel is the floor.
// This round: 256-bit stores (st.global.v8.f32, sm_100+) — halve store
// instruction count / L1tex wavefront-dispatch per byte. Thread t emits
// channels 8t..8t+7 (one v8 store = 32 B); 4 lanes share one input word;
// each warp store covers 1024 contiguous bytes.

constexpr int THREADS = 128;
constexpr int ITERS   = 8;                    // v8-stores per thread per chunk
constexpr int CHUNKW  = THREADS * ITERS;      // float8-groups per block = 1024
constexpr int WSTRIDE = THREADS / 4;          // input words per iteration step

__device__ __forceinline__ void stg_v8(float* p,
                                       float a, float b, float c, float d,
                                       float e, float f, float g, float h)
{
    asm volatile(
        "st.global.v8.f32 [%0], {%1, %2, %3, %4, %5, %6, %7, %8};"
        :: "l"(p), "f"(a), "f"(b), "f"(c), "f"(d),
                   "f"(e), "f"(f), "f"(g), "f"(h)
        : "memory");
}

__global__ void __launch_bounds__(THREADS)
base_encoder_kernel(const uint32_t* __restrict__ x,
                    float* __restrict__ out,
                    int n8)   // n8 = total output floats / 8
{
    const uint32_t ONE = 0x3f800000u;         // bit pattern of 1.0f

    int t0 = blockIdx.x * CHUNKW + threadIdx.x;   // first float8-group index
    int w0 = t0 >> 2;                         // input word = (8*t)/32 = t/4
    int c0 = (t0 & 3) * 8;                    // loop-invariant channel base

    if (t0 + (ITERS - 1) * THREADS < n8) {
        // Front-batch the independent loads (MLP = ITERS).
        uint32_t u[ITERS];
        #pragma unroll
        for (int i = 0; i < ITERS; i++)
            u[i] = __ldg(&x[w0 + i * WSTRIDE]);   // 4 lanes share one word

        #pragma unroll
        for (int i = 0; i < ITERS; i++) {
            uint32_t base = u[i] << c0;       // bit 31 of base == channel c0
            stg_v8(out + (size_t)(t0 + i * THREADS) * 8,
                __uint_as_float( (base >> 31)       * ONE),
                __uint_as_float(((base >> 30) & 1u) * ONE),
                __uint_as_float(((base >> 29) & 1u) * ONE),
                __uint_as_float(((base >> 28) & 1u) * ONE),
                __uint_as_float(((base >> 27) & 1u) * ONE),
                __uint_as_float(((base >> 26) & 1u) * ONE),
                __uint_as_float(((base >> 25) & 1u) * ONE),
                __uint_as_float(((base >> 24) & 1u) * ONE));
        }
    } else {
        // Tail path (unused for the fixed 4096x512x32 shape).
        #pragma unroll
        for (int i = 0; i < ITERS; i++) {
            int t = t0 + i * THREADS;
            if (t < n8) {
                uint32_t base = __ldg(&x[t >> 2]) << c0;
                stg_v8(out + (size_t)t * 8,
                    __uint_as_float( (base >> 31)       * ONE),
                    __uint_as_float(((base >> 30) & 1u) * ONE),
                    __uint_as_float(((base >> 29) & 1u) * ONE),
                    __uint_as_float(((base >> 28) & 1u) * ONE),
                    __uint_as_float(((base >> 27) & 1u) * ONE),
                    __uint_as_float(((base >> 26) & 1u) * ONE),
                    __uint_as_float(((base >> 25) & 1u) * ONE),
                    __uint_as_float(((base >> 24) & 1u) * ONE));
            }
        }
    }
}

extern "C" void kernel_launch(void* const* d_in, const int* in_sizes, int n_in,
                              void* d_out, int out_size)
{
    const uint32_t* x = (const uint32_t*)d_in[0];
    float* out = (float*)d_out;

    int n8 = out_size / 8;                    // 8,388,608 for 4096x512x32
    int blocks = (n8 + CHUNKW - 1) / CHUNKW;  // 8192

    base_encoder_kernel<<<blocks, THREADS>>>(x, out, n8);
}

// round 13
// speedup vs baseline: 1.0304x; 1.0304x over previous
#include <cuda_runtime.h>
#include <cstdint>

// BaseEncoder: out[b, f, c] = (bitcast<u32>(x[b,f]) >> (31 - c)) & 1  (float).
// c==0 is bit 31 (sign == (x<0) channel); c>=1 are bits 30..0 of |x|.
//
// FINAL (R8 configuration, frozen). Floor analysis across R8-R12:
// 264 MB crosses the SM<->L2 interface at ~6.3 TB/s = the measured
// path-independent B300 LTS chip cap (~6300 B/cyc). Persistent grids,
// CTA-granularity changes, and 256-bit stores were all neutral-or-worse;
// this mapping sits on the floor (~41.5-42 us kernel).
//
// Structure: each block owns a contiguous chunk of THREADS*ITERS float4s.
// Each thread front-batches ITERS independent LDGs (MLP=8; 8 lanes share
// one input word via broadcast), then computes + stores ITERS float4s.
// Each warp store instruction writes 512 contiguous bytes (perfectly
// coalesced STG.128). The bit-channel offset (t & 7) is loop-invariant
// because THREADS % 8 == 0, so the per-word pre-shift hoists.

constexpr int ITERS   = 8;
constexpr int THREADS = 256;
constexpr int CHUNK   = THREADS * ITERS;   // float4s per block = 2048
constexpr int WSTRIDE = THREADS / 8;       // input words per iteration step

__global__ void __launch_bounds__(THREADS)
base_encoder_kernel(const uint32_t* __restrict__ x,
                    float4* __restrict__ out,
                    int n4)
{
    const uint32_t ONE = 0x3f800000u;      // bit pattern of 1.0f

    int t0 = blockIdx.x * CHUNK + threadIdx.x;
    int w0 = t0 >> 3;                      // input word index for iteration 0
    int c0 = (t0 & 7) * 4;                 // loop-invariant bit-channel offset

    if (t0 + (ITERS - 1) * THREADS < n4) {
        // Fast path: all ITERS iterations in bounds. Front-batch the loads.
        uint32_t u[ITERS];
        #pragma unroll
        for (int i = 0; i < ITERS; i++)
            u[i] = __ldg(&x[w0 + i * WSTRIDE]);   // 8 lanes share one word

        #pragma unroll
        for (int i = 0; i < ITERS; i++) {
            uint32_t base = u[i] << c0;    // bit 31 of base == channel c0
            float4 v;
            v.x = __uint_as_float( (base >> 31)       * ONE);
            v.y = __uint_as_float(((base >> 30) & 1u) * ONE);
            v.z = __uint_as_float(((base >> 29) & 1u) * ONE);
            v.w = __uint_as_float(((base >> 28) & 1u) * ONE);
            out[t0 + i * THREADS] = v;
        }
    } else {
        // Tail path (unused for the fixed 4096x512x32 shape, kept for safety).
        #pragma unroll
        for (int i = 0; i < ITERS; i++) {
            int t = t0 + i * THREADS;
            if (t < n4) {
                uint32_t base = __ldg(&x[t >> 3]) << c0;
                float4 v;
                v.x = __uint_as_float( (base >> 31)       * ONE);
                v.y = __uint_as_float(((base >> 30) & 1u) * ONE);
                v.z = __uint_as_float(((base >> 29) & 1u) * ONE);
                v.w = __uint_as_float(((base >> 28) & 1u) * ONE);
                out[t] = v;
            }
        }
    }
}

extern "C" void kernel_launch(void* const* d_in, const int* in_sizes, int n_in,
                              void* d_out, int out_size)
{
    const uint32_t* x = (const uint32_t*)d_in[0];
    float4* out = (float4*)d_out;

    int n4 = out_size / 4;                 // 4096*512*32/4 = 16,777,216
    int blocks = (n4 + CHUNK - 1) / CHUNK; // 8192 for the fixed shape

    base_encoder_kernel<<<blocks, THREADS>>>(x, out, n4);
}